// round 8
// baseline (speedup 1.0000x reference)
#include <cuda_runtime.h>
#include <math.h>
#include <cstdint>

#define HIDDEN 2048
#define NHEADS 16
#define HDIM   128
#define BATCH  2
#define SEQ    2048
#define ROWS   (BATCH*SEQ)             // 4096
#define SCALE  0.08838834764831845f    // 1/sqrt(128)
#define SCALE2 0.12752041986642899f    // SCALE * log2(e)
#define LOG2E  1.4426950408889634f

// Scratch (allocation-guard-safe)
__device__ float g_Q[ROWS*HIDDEN];
__device__ float g_K[ROWS*HIDDEN];
__device__ float g_V[ROWS*HIDDEN];
__device__ float g_C[ROWS*HIDDEN];
__device__ float g_Xr[ROWS*HIDDEN];          // tf32-rounded hidden_states
__device__ float g_Wr[4*HIDDEN*HIDDEN];      // tf32-rounded Wq,Wk,Wv,Wo

// ---------------------------------------------------------------------------
// Helpers
// ---------------------------------------------------------------------------
__device__ __forceinline__ unsigned f2tf(float f) {
    unsigned u; asm("cvt.rna.tf32.f32 %0, %1;" : "=r"(u) : "f"(f)); return u;
}
__device__ __forceinline__ float ex2(float x) {
    float r; asm("ex2.approx.f32 %0, %1;" : "=f"(r) : "f"(x)); return r;
}
__device__ __forceinline__ uint32_t smem_u32(const void* p) {
    uint32_t a; asm("{ .reg .u64 t; cvta.to.shared.u64 t, %1; cvt.u32.u64 %0, t; }"
                    : "=r"(a) : "l"(p));
    return a;
}
__device__ __forceinline__ void cpa16(uint32_t dst, const void* src) {
    asm volatile("cp.async.cg.shared.global [%0], [%1], 16;" :: "r"(dst), "l"(src));
}
#define CP_COMMIT()  asm volatile("cp.async.commit_group;" ::: "memory")
#define CP_WAIT(n)   asm volatile("cp.async.wait_group %0;" :: "n"(n) : "memory")

__device__ __forceinline__ void mma8(float* c, const unsigned* a, const unsigned* b) {
    asm volatile(
        "mma.sync.aligned.m16n8k8.row.col.f32.tf32.tf32.f32 "
        "{%0,%1,%2,%3}, {%4,%5,%6,%7}, {%8,%9}, {%0,%1,%2,%3};"
        : "+f"(c[0]), "+f"(c[1]), "+f"(c[2]), "+f"(c[3])
        : "r"(a[0]), "r"(a[1]), "r"(a[2]), "r"(a[3]), "r"(b[0]), "r"(b[1]));
}

// ---------------------------------------------------------------------------
// Elementwise tf32 pre-round
// ---------------------------------------------------------------------------
__global__ void round_tf32_kernel(const float* __restrict__ in, float* __restrict__ out, int n4) {
    int i = blockIdx.x * blockDim.x + threadIdx.x;
    if (i < n4) {
        float4 v = ((const float4*)in)[i];
        float4 o;
        o.x = __uint_as_float(f2tf(v.x));
        o.y = __uint_as_float(f2tf(v.y));
        o.z = __uint_as_float(f2tf(v.z));
        o.w = __uint_as_float(f2tf(v.w));
        ((float4*)out)[i] = o;
    }
}

struct WPtrs { const float* w[4]; };

__global__ void round_w4_kernel(WPtrs ws, float* __restrict__ out, int nw4) {
    int i = blockIdx.x * blockDim.x + threadIdx.x;   // over 4*nw4
    int which = i / nw4;
    int off   = i - which * nw4;
    float4 v = ((const float4*)ws.w[which])[off];
    float4 o;
    o.x = __uint_as_float(f2tf(v.x));
    o.y = __uint_as_float(f2tf(v.y));
    o.z = __uint_as_float(f2tf(v.z));
    o.w = __uint_as_float(f2tf(v.w));
    ((float4*)out)[i] = o;
}

// ---------------------------------------------------------------------------
// TF32 mma.sync GEMM:  C[M,N] = A[M,K] @ W[N,K]^T + bias
// 128x256x32 block tile, 3-stage cp.async pipeline, 512 threads / 16 warps
// (4 per SMSP for latency hiding), warp tile 32x64 via 2x8 m16n8k8 tiles.
// Inputs must be pre-rounded to tf32 bit patterns.
// ---------------------------------------------------------------------------
#define GBM 128
#define GBN 256
#define GBK 32
#define AST 36
#define A_FLOATS (GBM*AST)
#define B_FLOATS (GBN*AST)
#define STG_FLOATS (A_FLOATS + B_FLOATS)
#define NSTAGE 3
#define GEMM_SMEM (NSTAGE*STG_FLOATS*4)
#define KCHUNKS (HIDDEN/GBK)

template<bool ROUND_OUT>
__global__ __launch_bounds__(512, 1) void tf32_gemm(
    const float* __restrict__ A, const float* __restrict__ W,
    const float* __restrict__ bias, float* __restrict__ C)
{
    extern __shared__ float sm[];
    const uint32_t sbase = smem_u32(sm);
    const int tid  = threadIdx.x;
    const int lane = tid & 31;
    const int warp = tid >> 5;
    const int g    = lane >> 2;
    const int l4   = lane & 3;
    const int mb   = (warp & 3) * 32;    // 4 row-warps
    const int nb   = (warp >> 2) * 64;   // 4 col-warps
    const int brow = blockIdx.y * GBM;
    const int bn   = blockIdx.x * GBN;

    float acc[2][8][4];
    #pragma unroll
    for (int i = 0; i < 2; i++)
        #pragma unroll
        for (int j = 0; j < 8; j++)
            #pragma unroll
            for (int t = 0; t < 4; t++) acc[i][j][t] = 0.f;

    auto load_stage = [&](int c, int s) {
        const uint32_t dA = sbase + (uint32_t)s * (STG_FLOATS * 4);
        const uint32_t dB = dA + A_FLOATS * 4;
        const int k0 = c * GBK;
        #pragma unroll
        for (int i = 0; i < 2; i++) {            // A: 128 rows x 32 floats
            int idx = tid + i * 512;
            int row = idx >> 3, kc = (idx & 7) * 4;
            cpa16(dA + row * (AST*4) + kc * 4,
                  &A[(size_t)(brow + row) * HIDDEN + k0 + kc]);
        }
        #pragma unroll
        for (int i = 0; i < 4; i++) {            // B: 256 rows x 32 floats
            int idx = tid + i * 512;
            int row = idx >> 3, kc = (idx & 7) * 4;
            cpa16(dB + row * (AST*4) + kc * 4,
                  &W[(size_t)(bn + row) * HIDDEN + k0 + kc]);
        }
        CP_COMMIT();
    };

    load_stage(0, 0);
    load_stage(1, 1);

    int s = 0;
    for (int c = 0; c < KCHUNKS; c++) {
        if (c == KCHUNKS - 1) { CP_WAIT(0); } else { CP_WAIT(1); }
        __syncthreads();
        if (c + 2 < KCHUNKS) load_stage(c + 2, (c + 2) % NSTAGE);

        const float* pA = sm + s * STG_FLOATS + mb * AST;
        const float* pB = sm + s * STG_FLOATS + A_FLOATS + nb * AST;

        #pragma unroll
        for (int ks = 0; ks < GBK; ks += 8) {
            unsigned af[2][4], bf[8][2];
            #pragma unroll
            for (int i = 0; i < 2; i++) {
                const float* p0 = pA + (i*16 + g) * AST + ks + l4;
                af[i][0] = __float_as_uint(p0[0]);
                af[i][1] = __float_as_uint(p0[8*AST]);
                af[i][2] = __float_as_uint(p0[4]);
                af[i][3] = __float_as_uint(p0[8*AST + 4]);
            }
            #pragma unroll
            for (int j = 0; j < 8; j++) {
                const float* p0 = pB + (j*8 + g) * AST + ks + l4;
                bf[j][0] = __float_as_uint(p0[0]);
                bf[j][1] = __float_as_uint(p0[4]);
            }
            #pragma unroll
            for (int i = 0; i < 2; i++)
                #pragma unroll
                for (int j = 0; j < 8; j++)
                    mma8(acc[i][j], af[i], bf[j]);
        }
        s = (s == NSTAGE - 1) ? 0 : s + 1;
    }

    #pragma unroll
    for (int i = 0; i < 2; i++) {
        const int r0 = brow + mb + i*16 + g;
        #pragma unroll
        for (int j = 0; j < 8; j++) {
            const int col = bn + nb + j*8 + 2*l4;
            float b0 = bias[col], b1 = bias[col + 1];
            float v0 = acc[i][j][0] + b0, v1 = acc[i][j][1] + b1;
            float v2 = acc[i][j][2] + b0, v3 = acc[i][j][3] + b1;
            if (ROUND_OUT) {
                v0 = __uint_as_float(f2tf(v0)); v1 = __uint_as_float(f2tf(v1));
                v2 = __uint_as_float(f2tf(v2)); v3 = __uint_as_float(f2tf(v3));
            }
            float2 w0 = {v0, v1}, w1 = {v2, v3};
            *(float2*)&C[(size_t)r0 * HIDDEN + col]       = w0;
            *(float2*)&C[(size_t)(r0 + 8) * HIDDEN + col] = w1;
        }
    }
}

// ---------------------------------------------------------------------------
// Flash attention, tf32 mma.sync, register-resident log2-domain softmax.
// 128 q-rows per block (512 threads, 16 warps), 128 keys per iter.
// S tile aliases the K tile (K dead after QK^T). Unchanged from R6.
// ---------------------------------------------------------------------------
#define AQ  128
#define AKK 128
#define QW  132    // row stride (floats): 128 + 4 pad
#define OQ  0
#define OK  (AQ*QW)                 // 16896   (K tile; S aliases this)
#define OV  (OK + AKK*QW)           // 33792
#define OMX (OV + AKK*QW)           // 50688
#define OL  (OMX + AQ)              // 50816
#define OPM (OL + AQ)               // 50944   pmax[4][128]
#define OPS (OPM + 512)             // 51456   psum[4][128]
#define ATT_FLOATS (OPS + 512)      // 51968
#define ATT_SMEM (ATT_FLOATS * 4)   // 207872 bytes

__global__ __launch_bounds__(512, 1) void attn_tf32(
    const float* __restrict__ Q, const float* __restrict__ K,
    const float* __restrict__ V, const float* __restrict__ mask,
    float* __restrict__ O)
{
    extern __shared__ float sm[];
    const uint32_t sbase = smem_u32(sm);
    float* sQ  = sm + OQ;
    float* sK  = sm + OK;
    float* sV  = sm + OV;
    float* sS  = sm + OK;      // alias: S overwrites K after QK^T
    float* sMx = sm + OMX;
    float* sL  = sm + OL;
    float* pmax = sm + OPM;
    float* psum = sm + OPS;

    const int tid  = threadIdx.x;
    const int lane = tid & 31;
    const int warp = tid >> 5;
    const int g    = lane >> 2;
    const int l4   = lane & 3;
    const int mb   = (warp & 3) * 32;
    const int wc   = warp >> 2;
    const int cb   = wc * 32;
    const int qt = blockIdx.x, h = blockIdx.y, b = blockIdx.z;
    const size_t base = (size_t)b * SEQ * HIDDEN + (size_t)h * HDIM;

    for (int it = tid; it < AQ*HDIM/4; it += 512) {
        int r = it >> 5, c = (it & 31) * 4;
        *(float4*)&sQ[r*QW + c] =
            *(const float4*)&Q[base + (size_t)(qt*AQ + r)*HIDDEN + c];
    }
    if (tid < AQ) { sMx[tid] = -1e30f; sL[tid] = 0.f; }

    float oacc[2][4][4];
    #pragma unroll
    for (int i = 0; i < 2; i++)
        #pragma unroll
        for (int j = 0; j < 4; j++)
            #pragma unroll
            for (int t = 0; t < 4; t++) oacc[i][j][t] = 0.f;

    for (int kt = 0; kt < SEQ/AKK; kt++) {      // 16 iterations
        __syncthreads();   // (1) prior PV done: K/S, V buffers + partials free

        {
            const uint32_t kdst = sbase + OK*4;
            const uint32_t vdst = sbase + OV*4;
            #pragma unroll
            for (int i = 0; i < 8; i++) {
                int it = tid + i*512;
                int r = it >> 5, c = (it & 31) * 4;
                cpa16(kdst + (r*QW + c)*4,
                      &K[base + (size_t)(kt*AKK + r)*HIDDEN + c]);
            }
            CP_COMMIT();
            #pragma unroll
            for (int i = 0; i < 8; i++) {
                int it = tid + i*512;
                int r = it >> 5, c = (it & 31) * 4;
                cpa16(vdst + (r*QW + c)*4,
                      &V[base + (size_t)(kt*AKK + r)*HIDDEN + c]);
            }
            CP_COMMIT();
        }

        float ml[4][2];
        {
            const float* mrow = &mask[(size_t)b*SEQ + kt*AKK];
            #pragma unroll
            for (int j = 0; j < 4; j++) {
                float2 mv = *(const float2*)&mrow[cb + j*8 + 2*l4];
                ml[j][0] = mv.x * LOG2E;
                ml[j][1] = mv.y * LOG2E;
            }
        }

        CP_WAIT(1);        // K arrived (V may still be in flight)
        __syncthreads();   // (2) K visible to all warps

        float sacc[2][4][4];
        #pragma unroll
        for (int i = 0; i < 2; i++)
            #pragma unroll
            for (int j = 0; j < 4; j++)
                #pragma unroll
                for (int t = 0; t < 4; t++) sacc[i][j][t] = 0.f;

        #pragma unroll
        for (int ks = 0; ks < HDIM; ks += 8) {
            unsigned af[2][4], bf[4][2];
            #pragma unroll
            for (int i = 0; i < 2; i++) {
                const float* p0 = &sQ[(mb + i*16 + g)*QW + ks + l4];
                af[i][0] = __float_as_uint(p0[0]);
                af[i][1] = __float_as_uint(p0[8*QW]);
                af[i][2] = __float_as_uint(p0[4]);
                af[i][3] = __float_as_uint(p0[8*QW + 4]);
            }
            #pragma unroll
            for (int j = 0; j < 4; j++) {
                const float* p0 = &sK[(cb + j*8 + g)*QW + ks + l4];
                bf[j][0] = __float_as_uint(p0[0]);
                bf[j][1] = __float_as_uint(p0[4]);
            }
            #pragma unroll
            for (int i = 0; i < 2; i++)
                #pragma unroll
                for (int j = 0; j < 4; j++)
                    mma8(sacc[i][j], af[i], bf[j]);
        }

        #pragma unroll
        for (int i = 0; i < 2; i++)
            #pragma unroll
            for (int j = 0; j < 4; j++) {
                sacc[i][j][0] = sacc[i][j][0]*SCALE2 + ml[j][0];
                sacc[i][j][1] = sacc[i][j][1]*SCALE2 + ml[j][1];
                sacc[i][j][2] = sacc[i][j][2]*SCALE2 + ml[j][0];
                sacc[i][j][3] = sacc[i][j][3]*SCALE2 + ml[j][1];
            }

        float mloc[2][2];
        #pragma unroll
        for (int i = 0; i < 2; i++)
            #pragma unroll
            for (int p = 0; p < 2; p++) {
                float m = -1e30f;
                #pragma unroll
                for (int j = 0; j < 4; j++)
                    m = fmaxf(m, fmaxf(sacc[i][j][2*p], sacc[i][j][2*p+1]));
                m = fmaxf(m, __shfl_xor_sync(0xffffffffu, m, 1));
                m = fmaxf(m, __shfl_xor_sync(0xffffffffu, m, 2));
                mloc[i][p] = m;
            }
        if (l4 == 0) {
            #pragma unroll
            for (int i = 0; i < 2; i++)
                #pragma unroll
                for (int p = 0; p < 2; p++)
                    pmax[wc*AQ + mb + i*16 + p*8 + g] = mloc[i][p];
        }
        __syncthreads();   // (3) pmax visible; ALL K reads complete

        float mtv[2][2], fv[2][2], lsum[2][2];
        #pragma unroll
        for (int i = 0; i < 2; i++)
            #pragma unroll
            for (int p = 0; p < 2; p++) {
                int r = mb + i*16 + p*8 + g;
                float mo = sMx[r];
                float mt = fmaxf(fmaxf(pmax[r], pmax[AQ+r]),
                                 fmaxf(pmax[2*AQ+r], pmax[3*AQ+r]));
                mt = fmaxf(mo, mt);
                mtv[i][p] = mt;
                fv[i][p]  = ex2(mo - mt);
                lsum[i][p] = 0.f;
            }
        #pragma unroll
        for (int i = 0; i < 2; i++)
            #pragma unroll
            for (int j = 0; j < 4; j++)
                #pragma unroll
                for (int p = 0; p < 2; p++) {
                    float p0 = __uint_as_float(f2tf(ex2(sacc[i][j][2*p]   - mtv[i][p])));
                    float p1 = __uint_as_float(f2tf(ex2(sacc[i][j][2*p+1] - mtv[i][p])));
                    lsum[i][p] += p0 + p1;
                    float2 pv = {p0, p1};
                    *(float2*)&sS[(mb + i*16 + p*8 + g)*QW + cb + j*8 + 2*l4] = pv;
                }
        #pragma unroll
        for (int i = 0; i < 2; i++)
            #pragma unroll
            for (int p = 0; p < 2; p++) {
                float l = lsum[i][p];
                l += __shfl_xor_sync(0xffffffffu, l, 1);
                l += __shfl_xor_sync(0xffffffffu, l, 2);
                lsum[i][p] = l;
            }
        if (l4 == 0) {
            #pragma unroll
            for (int i = 0; i < 2; i++)
                #pragma unroll
                for (int p = 0; p < 2; p++)
                    psum[wc*AQ + mb + i*16 + p*8 + g] = lsum[i][p];
        }

        CP_WAIT(0);        // V arrived
        __syncthreads();   // (4) psum + P + V visible

        if (wc == 0 && l4 == 0) {
            #pragma unroll
            for (int i = 0; i < 2; i++)
                #pragma unroll
                for (int p = 0; p < 2; p++) {
                    int r = mb + i*16 + p*8 + g;
                    float ls = psum[r] + psum[AQ+r] + psum[2*AQ+r] + psum[3*AQ+r];
                    sL[r]  = sL[r]*fv[i][p] + ls;
                    sMx[r] = mtv[i][p];
                }
        }

        #pragma unroll
        for (int i = 0; i < 2; i++)
            #pragma unroll
            for (int j = 0; j < 4; j++) {
                oacc[i][j][0] *= fv[i][0]; oacc[i][j][1] *= fv[i][0];
                oacc[i][j][2] *= fv[i][1]; oacc[i][j][3] *= fv[i][1];
            }
        #pragma unroll
        for (int ks = 0; ks < AKK; ks += 8) {
            unsigned af[2][4], bf[4][2];
            #pragma unroll
            for (int i = 0; i < 2; i++) {
                const float* p0 = &sS[(mb + i*16 + g)*QW + ks + l4];
                af[i][0] = __float_as_uint(p0[0]);
                af[i][1] = __float_as_uint(p0[8*QW]);
                af[i][2] = __float_as_uint(p0[4]);
                af[i][3] = __float_as_uint(p0[8*QW + 4]);
            }
            #pragma unroll
            for (int j = 0; j < 4; j++) {
                const float* p0 = &sV[(ks + l4)*QW + cb + j*8 + g];
                bf[j][0] = __float_as_uint(p0[0]);
                bf[j][1] = __float_as_uint(p0[4*QW]);
            }
            #pragma unroll
            for (int i = 0; i < 2; i++)
                #pragma unroll
                for (int j = 0; j < 4; j++)
                    mma8(oacc[i][j], af[i], bf[j]);
        }
    }

    __syncthreads();       // final sL updates visible

    #pragma unroll
    for (int i = 0; i < 2; i++) {
        float i0 = 1.f / sL[mb + i*16 + g];
        float i1 = 1.f / sL[mb + i*16 + g + 8];
        #pragma unroll
        for (int j = 0; j < 4; j++) {
            int col = cb + j*8 + 2*l4;
            size_t r0 = base + (size_t)(qt*AQ + mb + i*16 + g    )*HIDDEN + col;
            size_t r1 = base + (size_t)(qt*AQ + mb + i*16 + g + 8)*HIDDEN + col;
            float2 v0 = { __uint_as_float(f2tf(oacc[i][j][0]*i0)),
                          __uint_as_float(f2tf(oacc[i][j][1]*i0)) };
            float2 v1 = { __uint_as_float(f2tf(oacc[i][j][2]*i1)),
                          __uint_as_float(f2tf(oacc[i][j][3]*i1)) };
            *(float2*)&O[r0] = v0;
            *(float2*)&O[r1] = v1;
        }
    }
}

// ---------------------------------------------------------------------------
extern "C" void kernel_launch(void* const* d_in, const int* in_sizes, int n_in,
                              void* d_out, int out_size) {
    const float* X    = (const float*)d_in[0];
    const float* mask = (const float*)d_in[1];
    const float* Wq   = (const float*)d_in[2];
    const float* bq   = (const float*)d_in[3];
    const float* Wk   = (const float*)d_in[4];
    const float* bk   = (const float*)d_in[5];
    const float* Wv   = (const float*)d_in[6];
    const float* bv   = (const float*)d_in[7];
    const float* Wo   = (const float*)d_in[8];
    const float* bo   = (const float*)d_in[9];
    float* out = (float*)d_out;

    float *qp, *kp, *vp, *cp, *xr, *wr;
    cudaGetSymbolAddress((void**)&qp, g_Q);
    cudaGetSymbolAddress((void**)&kp, g_K);
    cudaGetSymbolAddress((void**)&vp, g_V);
    cudaGetSymbolAddress((void**)&cp, g_C);
    cudaGetSymbolAddress((void**)&xr, g_Xr);
    cudaGetSymbolAddress((void**)&wr, g_Wr);

    const int NX4 = ROWS*HIDDEN/4, NW4 = HIDDEN*HIDDEN/4;
    round_tf32_kernel<<<(NX4+255)/256, 256>>>(X, xr, NX4);
    WPtrs ws; ws.w[0] = Wq; ws.w[1] = Wk; ws.w[2] = Wv; ws.w[3] = Wo;
    round_w4_kernel<<<(4*NW4)/256, 256>>>(ws, wr, NW4);

    cudaFuncSetAttribute(tf32_gemm<true>,  cudaFuncAttributeMaxDynamicSharedMemorySize, GEMM_SMEM);
    cudaFuncSetAttribute(tf32_gemm<false>, cudaFuncAttributeMaxDynamicSharedMemorySize, GEMM_SMEM);

    dim3 ggrid(HIDDEN/GBN, ROWS/GBM);   // (8, 32)
    tf32_gemm<true><<<ggrid, 512, GEMM_SMEM>>>(xr, wr + 0*HIDDEN*HIDDEN, bq, qp);
    tf32_gemm<true><<<ggrid, 512, GEMM_SMEM>>>(xr, wr + 1*HIDDEN*HIDDEN, bk, kp);
    tf32_gemm<true><<<ggrid, 512, GEMM_SMEM>>>(xr, wr + 2*HIDDEN*HIDDEN, bv, vp);

    cudaFuncSetAttribute(attn_tf32, cudaFuncAttributeMaxDynamicSharedMemorySize, (int)ATT_SMEM);
    dim3 agrid(SEQ/AQ, NHEADS, BATCH);  // (16, 16, 2)
    attn_tf32<<<agrid, 512, ATT_SMEM>>>(qp, kp, vp, mask, cp);

    tf32_gemm<false><<<ggrid, 512, GEMM_SMEM>>>(cp, wr + 3*HIDDEN*HIDDEN, bo, out);
}

// round 9
// speedup vs baseline: 1.0878x; 1.0878x over previous
#include <cuda_runtime.h>
#include <math.h>
#include <cstdint>

#define HIDDEN 2048
#define NHEADS 16
#define HDIM   128
#define BATCH  2
#define SEQ    2048
#define ROWS   (BATCH*SEQ)             // 4096
#define SCALE  0.08838834764831845f    // 1/sqrt(128)
#define SCALE2 0.12752041986642899f    // SCALE * log2(e)
#define LOG2E  1.4426950408889634f

// Scratch (allocation-guard-safe)
__device__ float g_Q[ROWS*HIDDEN];
__device__ float g_K[ROWS*HIDDEN];
__device__ float g_V[ROWS*HIDDEN];
__device__ float g_C[ROWS*HIDDEN];
__device__ float g_Xr[ROWS*HIDDEN];          // tf32-rounded hidden_states
__device__ float g_Wr[4*HIDDEN*HIDDEN];      // tf32-rounded Wq,Wk,Wv,Wo

// ---------------------------------------------------------------------------
// Helpers
// ---------------------------------------------------------------------------
__device__ __forceinline__ unsigned f2tf(float f) {
    unsigned u; asm("cvt.rna.tf32.f32 %0, %1;" : "=r"(u) : "f"(f)); return u;
}
__device__ __forceinline__ float ex2(float x) {
    float r; asm("ex2.approx.f32 %0, %1;" : "=f"(r) : "f"(x)); return r;
}
__device__ __forceinline__ uint32_t smem_u32(const void* p) {
    uint32_t a; asm("{ .reg .u64 t; cvta.to.shared.u64 t, %1; cvt.u32.u64 %0, t; }"
                    : "=r"(a) : "l"(p));
    return a;
}
__device__ __forceinline__ void cpa16(uint32_t dst, const void* src) {
    asm volatile("cp.async.cg.shared.global [%0], [%1], 16;" :: "r"(dst), "l"(src));
}
#define CP_COMMIT()  asm volatile("cp.async.commit_group;" ::: "memory")
#define CP_WAIT(n)   asm volatile("cp.async.wait_group %0;" :: "n"(n) : "memory")

__device__ __forceinline__ void mma8(float* c, const unsigned* a, const unsigned* b) {
    asm volatile(
        "mma.sync.aligned.m16n8k8.row.col.f32.tf32.tf32.f32 "
        "{%0,%1,%2,%3}, {%4,%5,%6,%7}, {%8,%9}, {%0,%1,%2,%3};"
        : "+f"(c[0]), "+f"(c[1]), "+f"(c[2]), "+f"(c[3])
        : "r"(a[0]), "r"(a[1]), "r"(a[2]), "r"(a[3]), "r"(b[0]), "r"(b[1]));
}

// ---------------------------------------------------------------------------
// Elementwise tf32 pre-round
// ---------------------------------------------------------------------------
__global__ void round_tf32_kernel(const float* __restrict__ in, float* __restrict__ out, int n4) {
    int i = blockIdx.x * blockDim.x + threadIdx.x;
    if (i < n4) {
        float4 v = ((const float4*)in)[i];
        float4 o;
        o.x = __uint_as_float(f2tf(v.x));
        o.y = __uint_as_float(f2tf(v.y));
        o.z = __uint_as_float(f2tf(v.z));
        o.w = __uint_as_float(f2tf(v.w));
        ((float4*)out)[i] = o;
    }
}

struct WPtrs { const float* w[4]; };

__global__ void round_w4_kernel(WPtrs ws, float* __restrict__ out, int nw4) {
    int i = blockIdx.x * blockDim.x + threadIdx.x;   // over 4*nw4
    int which = i / nw4;
    int off   = i - which * nw4;
    float4 v = ((const float4*)ws.w[which])[off];
    float4 o;
    o.x = __uint_as_float(f2tf(v.x));
    o.y = __uint_as_float(f2tf(v.y));
    o.z = __uint_as_float(f2tf(v.z));
    o.w = __uint_as_float(f2tf(v.w));
    ((float4*)out)[i] = o;
}

// ---------------------------------------------------------------------------
// TF32 mma.sync GEMM:  out[M, 2048] blocks = A[M,K] @ W[N_total,K]^T + bias
// 128x128x32 CTA tile, 4 warps (64x64 warp tile, 1.0 LDS/MMA), 3-stage
// cp.async pipeline, 2 CTAs per SM (barrier bubbles covered by co-CTA).
// W may stack up to 3 weight matrices (fused QKV); the output/bias for a
// block column is selected by bn>>11 (each 128-col block is within one).
// ---------------------------------------------------------------------------
#define GBM 128
#define GBN 128
#define GBK 32
#define AST 36
#define A_FLOATS (GBM*AST)                 // 4608
#define B_FLOATS (GBN*AST)                 // 4608
#define STG_FLOATS (A_FLOATS + B_FLOATS)   // 9216
#define NSTAGE 3
#define GEMM_SMEM (NSTAGE*STG_FLOATS*4)    // 110592 B
#define KCHUNKS (HIDDEN/GBK)               // 64

struct GemmOuts {
    float* out[3];
    const float* bias[3];
};

template<bool ROUND_OUT>
__global__ __launch_bounds__(128, 2) void tf32_gemm(
    const float* __restrict__ A, const float* __restrict__ W, GemmOuts go)
{
    extern __shared__ float sm[];
    const uint32_t sbase = smem_u32(sm);
    const int tid  = threadIdx.x;
    const int lane = tid & 31;
    const int warp = tid >> 5;          // 0..3
    const int g    = lane >> 2;
    const int l4   = lane & 3;
    const int mb   = (warp & 1) * 64;
    const int nb   = (warp >> 1) * 64;
    const int brow = blockIdx.y * GBM;
    const int bnT  = blockIdx.x * GBN;          // column in stacked-N space
    const int which = bnT >> 11;                // which weight matrix
    const int bn    = bnT & 2047;               // column within output
    float* C = go.out[which];
    const float* bias = go.bias[which];

    float acc[4][8][4];
    #pragma unroll
    for (int i = 0; i < 4; i++)
        #pragma unroll
        for (int j = 0; j < 8; j++)
            #pragma unroll
            for (int t = 0; t < 4; t++) acc[i][j][t] = 0.f;

    auto load_stage = [&](int c, int s) {
        const uint32_t dA = sbase + (uint32_t)s * (STG_FLOATS * 4);
        const uint32_t dB = dA + A_FLOATS * 4;
        const int k0 = c * GBK;
        #pragma unroll
        for (int i = 0; i < 8; i++) {            // A: 128 rows x 32 floats
            int idx = tid + i * 128;
            int row = idx >> 3, kc = (idx & 7) * 4;
            cpa16(dA + row * (AST*4) + kc * 4,
                  &A[(size_t)(brow + row) * HIDDEN + k0 + kc]);
        }
        #pragma unroll
        for (int i = 0; i < 8; i++) {            // B: 128 rows x 32 floats
            int idx = tid + i * 128;
            int row = idx >> 3, kc = (idx & 7) * 4;
            cpa16(dB + row * (AST*4) + kc * 4,
                  &W[(size_t)(bnT + row) * HIDDEN + k0 + kc]);
        }
        CP_COMMIT();
    };

    load_stage(0, 0);
    load_stage(1, 1);

    int s = 0;
    for (int c = 0; c < KCHUNKS; c++) {
        if (c == KCHUNKS - 1) { CP_WAIT(0); } else { CP_WAIT(1); }
        __syncthreads();
        if (c + 2 < KCHUNKS) load_stage(c + 2, (c + 2) % NSTAGE);

        const float* pA = sm + s * STG_FLOATS + mb * AST;
        const float* pB = sm + s * STG_FLOATS + A_FLOATS + nb * AST;

        #pragma unroll
        for (int ks = 0; ks < GBK; ks += 8) {
            unsigned af[4][4], bf[8][2];
            #pragma unroll
            for (int i = 0; i < 4; i++) {
                const float* p0 = pA + (i*16 + g) * AST + ks + l4;
                af[i][0] = __float_as_uint(p0[0]);
                af[i][1] = __float_as_uint(p0[8*AST]);
                af[i][2] = __float_as_uint(p0[4]);
                af[i][3] = __float_as_uint(p0[8*AST + 4]);
            }
            #pragma unroll
            for (int j = 0; j < 8; j++) {
                const float* p0 = pB + (j*8 + g) * AST + ks + l4;
                bf[j][0] = __float_as_uint(p0[0]);
                bf[j][1] = __float_as_uint(p0[4]);
            }
            #pragma unroll
            for (int i = 0; i < 4; i++)
                #pragma unroll
                for (int j = 0; j < 8; j++)
                    mma8(acc[i][j], af[i], bf[j]);
        }
        s = (s == NSTAGE - 1) ? 0 : s + 1;
    }

    #pragma unroll
    for (int i = 0; i < 4; i++) {
        const int r0 = brow + mb + i*16 + g;
        #pragma unroll
        for (int j = 0; j < 8; j++) {
            const int col = bn + nb + j*8 + 2*l4;
            float b0 = bias[col], b1 = bias[col + 1];
            float v0 = acc[i][j][0] + b0, v1 = acc[i][j][1] + b1;
            float v2 = acc[i][j][2] + b0, v3 = acc[i][j][3] + b1;
            if (ROUND_OUT) {
                v0 = __uint_as_float(f2tf(v0)); v1 = __uint_as_float(f2tf(v1));
                v2 = __uint_as_float(f2tf(v2)); v3 = __uint_as_float(f2tf(v3));
            }
            float2 w0 = {v0, v1}, w1 = {v2, v3};
            *(float2*)&C[(size_t)r0 * HIDDEN + col]       = w0;
            *(float2*)&C[(size_t)(r0 + 8) * HIDDEN + col] = w1;
        }
    }
}

// ---------------------------------------------------------------------------
// Flash attention, tf32 mma.sync, register-resident log2-domain softmax.
// 128 q-rows per block (512 threads, 16 warps), 128 keys per iter.
// S tile aliases the K tile (K dead after QK^T). Unchanged from R7.
// ---------------------------------------------------------------------------
#define AQ  128
#define AKK 128
#define QW  132    // row stride (floats): 128 + 4 pad
#define OQ  0
#define OK  (AQ*QW)                 // 16896   (K tile; S aliases this)
#define OV  (OK + AKK*QW)           // 33792
#define OMX (OV + AKK*QW)           // 50688
#define OL  (OMX + AQ)              // 50816
#define OPM (OL + AQ)               // 50944   pmax[4][128]
#define OPS (OPM + 512)             // 51456   psum[4][128]
#define ATT_FLOATS (OPS + 512)      // 51968
#define ATT_SMEM (ATT_FLOATS * 4)   // 207872 bytes

__global__ __launch_bounds__(512, 1) void attn_tf32(
    const float* __restrict__ Q, const float* __restrict__ K,
    const float* __restrict__ V, const float* __restrict__ mask,
    float* __restrict__ O)
{
    extern __shared__ float sm[];
    const uint32_t sbase = smem_u32(sm);
    float* sQ  = sm + OQ;
    float* sK  = sm + OK;
    float* sV  = sm + OV;
    float* sS  = sm + OK;      // alias: S overwrites K after QK^T
    float* sMx = sm + OMX;
    float* sL  = sm + OL;
    float* pmax = sm + OPM;
    float* psum = sm + OPS;

    const int tid  = threadIdx.x;
    const int lane = tid & 31;
    const int warp = tid >> 5;
    const int g    = lane >> 2;
    const int l4   = lane & 3;
    const int mb   = (warp & 3) * 32;
    const int wc   = warp >> 2;
    const int cb   = wc * 32;
    const int qt = blockIdx.x, h = blockIdx.y, b = blockIdx.z;
    const size_t base = (size_t)b * SEQ * HIDDEN + (size_t)h * HDIM;

    for (int it = tid; it < AQ*HDIM/4; it += 512) {
        int r = it >> 5, c = (it & 31) * 4;
        *(float4*)&sQ[r*QW + c] =
            *(const float4*)&Q[base + (size_t)(qt*AQ + r)*HIDDEN + c];
    }
    if (tid < AQ) { sMx[tid] = -1e30f; sL[tid] = 0.f; }

    float oacc[2][4][4];
    #pragma unroll
    for (int i = 0; i < 2; i++)
        #pragma unroll
        for (int j = 0; j < 4; j++)
            #pragma unroll
            for (int t = 0; t < 4; t++) oacc[i][j][t] = 0.f;

    for (int kt = 0; kt < SEQ/AKK; kt++) {      // 16 iterations
        __syncthreads();   // (1) prior PV done: K/S, V buffers + partials free

        {
            const uint32_t kdst = sbase + OK*4;
            const uint32_t vdst = sbase + OV*4;
            #pragma unroll
            for (int i = 0; i < 8; i++) {
                int it = tid + i*512;
                int r = it >> 5, c = (it & 31) * 4;
                cpa16(kdst + (r*QW + c)*4,
                      &K[base + (size_t)(kt*AKK + r)*HIDDEN + c]);
            }
            CP_COMMIT();
            #pragma unroll
            for (int i = 0; i < 8; i++) {
                int it = tid + i*512;
                int r = it >> 5, c = (it & 31) * 4;
                cpa16(vdst + (r*QW + c)*4,
                      &V[base + (size_t)(kt*AKK + r)*HIDDEN + c]);
            }
            CP_COMMIT();
        }

        float ml[4][2];
        {
            const float* mrow = &mask[(size_t)b*SEQ + kt*AKK];
            #pragma unroll
            for (int j = 0; j < 4; j++) {
                float2 mv = *(const float2*)&mrow[cb + j*8 + 2*l4];
                ml[j][0] = mv.x * LOG2E;
                ml[j][1] = mv.y * LOG2E;
            }
        }

        CP_WAIT(1);        // K arrived (V may still be in flight)
        __syncthreads();   // (2) K visible to all warps

        float sacc[2][4][4];
        #pragma unroll
        for (int i = 0; i < 2; i++)
            #pragma unroll
            for (int j = 0; j < 4; j++)
                #pragma unroll
                for (int t = 0; t < 4; t++) sacc[i][j][t] = 0.f;

        #pragma unroll
        for (int ks = 0; ks < HDIM; ks += 8) {
            unsigned af[2][4], bf[4][2];
            #pragma unroll
            for (int i = 0; i < 2; i++) {
                const float* p0 = &sQ[(mb + i*16 + g)*QW + ks + l4];
                af[i][0] = __float_as_uint(p0[0]);
                af[i][1] = __float_as_uint(p0[8*QW]);
                af[i][2] = __float_as_uint(p0[4]);
                af[i][3] = __float_as_uint(p0[8*QW + 4]);
            }
            #pragma unroll
            for (int j = 0; j < 4; j++) {
                const float* p0 = &sK[(cb + j*8 + g)*QW + ks + l4];
                bf[j][0] = __float_as_uint(p0[0]);
                bf[j][1] = __float_as_uint(p0[4]);
            }
            #pragma unroll
            for (int i = 0; i < 2; i++)
                #pragma unroll
                for (int j = 0; j < 4; j++)
                    mma8(sacc[i][j], af[i], bf[j]);
        }

        #pragma unroll
        for (int i = 0; i < 2; i++)
            #pragma unroll
            for (int j = 0; j < 4; j++) {
                sacc[i][j][0] = sacc[i][j][0]*SCALE2 + ml[j][0];
                sacc[i][j][1] = sacc[i][j][1]*SCALE2 + ml[j][1];
                sacc[i][j][2] = sacc[i][j][2]*SCALE2 + ml[j][0];
                sacc[i][j][3] = sacc[i][j][3]*SCALE2 + ml[j][1];
            }

        float mloc[2][2];
        #pragma unroll
        for (int i = 0; i < 2; i++)
            #pragma unroll
            for (int p = 0; p < 2; p++) {
                float m = -1e30f;
                #pragma unroll
                for (int j = 0; j < 4; j++)
                    m = fmaxf(m, fmaxf(sacc[i][j][2*p], sacc[i][j][2*p+1]));
                m = fmaxf(m, __shfl_xor_sync(0xffffffffu, m, 1));
                m = fmaxf(m, __shfl_xor_sync(0xffffffffu, m, 2));
                mloc[i][p] = m;
            }
        if (l4 == 0) {
            #pragma unroll
            for (int i = 0; i < 2; i++)
                #pragma unroll
                for (int p = 0; p < 2; p++)
                    pmax[wc*AQ + mb + i*16 + p*8 + g] = mloc[i][p];
        }
        __syncthreads();   // (3) pmax visible; ALL K reads complete

        float mtv[2][2], fv[2][2], lsum[2][2];
        #pragma unroll
        for (int i = 0; i < 2; i++)
            #pragma unroll
            for (int p = 0; p < 2; p++) {
                int r = mb + i*16 + p*8 + g;
                float mo = sMx[r];
                float mt = fmaxf(fmaxf(pmax[r], pmax[AQ+r]),
                                 fmaxf(pmax[2*AQ+r], pmax[3*AQ+r]));
                mt = fmaxf(mo, mt);
                mtv[i][p] = mt;
                fv[i][p]  = ex2(mo - mt);
                lsum[i][p] = 0.f;
            }
        #pragma unroll
        for (int i = 0; i < 2; i++)
            #pragma unroll
            for (int j = 0; j < 4; j++)
                #pragma unroll
                for (int p = 0; p < 2; p++) {
                    float p0 = __uint_as_float(f2tf(ex2(sacc[i][j][2*p]   - mtv[i][p])));
                    float p1 = __uint_as_float(f2tf(ex2(sacc[i][j][2*p+1] - mtv[i][p])));
                    lsum[i][p] += p0 + p1;
                    float2 pv = {p0, p1};
                    *(float2*)&sS[(mb + i*16 + p*8 + g)*QW + cb + j*8 + 2*l4] = pv;
                }
        #pragma unroll
        for (int i = 0; i < 2; i++)
            #pragma unroll
            for (int p = 0; p < 2; p++) {
                float l = lsum[i][p];
                l += __shfl_xor_sync(0xffffffffu, l, 1);
                l += __shfl_xor_sync(0xffffffffu, l, 2);
                lsum[i][p] = l;
            }
        if (l4 == 0) {
            #pragma unroll
            for (int i = 0; i < 2; i++)
                #pragma unroll
                for (int p = 0; p < 2; p++)
                    psum[wc*AQ + mb + i*16 + p*8 + g] = lsum[i][p];
        }

        CP_WAIT(0);        // V arrived
        __syncthreads();   // (4) psum + P + V visible

        if (wc == 0 && l4 == 0) {
            #pragma unroll
            for (int i = 0; i < 2; i++)
                #pragma unroll
                for (int p = 0; p < 2; p++) {
                    int r = mb + i*16 + p*8 + g;
                    float ls = psum[r] + psum[AQ+r] + psum[2*AQ+r] + psum[3*AQ+r];
                    sL[r]  = sL[r]*fv[i][p] + ls;
                    sMx[r] = mtv[i][p];
                }
        }

        #pragma unroll
        for (int i = 0; i < 2; i++)
            #pragma unroll
            for (int j = 0; j < 4; j++) {
                oacc[i][j][0] *= fv[i][0]; oacc[i][j][1] *= fv[i][0];
                oacc[i][j][2] *= fv[i][1]; oacc[i][j][3] *= fv[i][1];
            }
        #pragma unroll
        for (int ks = 0; ks < AKK; ks += 8) {
            unsigned af[2][4], bf[4][2];
            #pragma unroll
            for (int i = 0; i < 2; i++) {
                const float* p0 = &sS[(mb + i*16 + g)*QW + ks + l4];
                af[i][0] = __float_as_uint(p0[0]);
                af[i][1] = __float_as_uint(p0[8*QW]);
                af[i][2] = __float_as_uint(p0[4]);
                af[i][3] = __float_as_uint(p0[8*QW + 4]);
            }
            #pragma unroll
            for (int j = 0; j < 4; j++) {
                const float* p0 = &sV[(ks + l4)*QW + cb + j*8 + g];
                bf[j][0] = __float_as_uint(p0[0]);
                bf[j][1] = __float_as_uint(p0[4*QW]);
            }
            #pragma unroll
            for (int i = 0; i < 2; i++)
                #pragma unroll
                for (int j = 0; j < 4; j++)
                    mma8(oacc[i][j], af[i], bf[j]);
        }
    }

    __syncthreads();       // final sL updates visible

    #pragma unroll
    for (int i = 0; i < 2; i++) {
        float i0 = 1.f / sL[mb + i*16 + g];
        float i1 = 1.f / sL[mb + i*16 + g + 8];
        #pragma unroll
        for (int j = 0; j < 4; j++) {
            int col = cb + j*8 + 2*l4;
            size_t r0 = base + (size_t)(qt*AQ + mb + i*16 + g    )*HIDDEN + col;
            size_t r1 = base + (size_t)(qt*AQ + mb + i*16 + g + 8)*HIDDEN + col;
            float2 v0 = { __uint_as_float(f2tf(oacc[i][j][0]*i0)),
                          __uint_as_float(f2tf(oacc[i][j][1]*i0)) };
            float2 v1 = { __uint_as_float(f2tf(oacc[i][j][2]*i1)),
                          __uint_as_float(f2tf(oacc[i][j][3]*i1)) };
            *(float2*)&O[r0] = v0;
            *(float2*)&O[r1] = v1;
        }
    }
}

// ---------------------------------------------------------------------------
extern "C" void kernel_launch(void* const* d_in, const int* in_sizes, int n_in,
                              void* d_out, int out_size) {
    const float* X    = (const float*)d_in[0];
    const float* mask = (const float*)d_in[1];
    const float* Wq   = (const float*)d_in[2];
    const float* bq   = (const float*)d_in[3];
    const float* Wk   = (const float*)d_in[4];
    const float* bk   = (const float*)d_in[5];
    const float* Wv   = (const float*)d_in[6];
    const float* bv   = (const float*)d_in[7];
    const float* Wo   = (const float*)d_in[8];
    const float* bo   = (const float*)d_in[9];
    float* out = (float*)d_out;

    float *qp, *kp, *vp, *cp, *xr, *wr;
    cudaGetSymbolAddress((void**)&qp, g_Q);
    cudaGetSymbolAddress((void**)&kp, g_K);
    cudaGetSymbolAddress((void**)&vp, g_V);
    cudaGetSymbolAddress((void**)&cp, g_C);
    cudaGetSymbolAddress((void**)&xr, g_Xr);
    cudaGetSymbolAddress((void**)&wr, g_Wr);

    const int NX4 = ROWS*HIDDEN/4, NW4 = HIDDEN*HIDDEN/4;
    round_tf32_kernel<<<(NX4+255)/256, 256>>>(X, xr, NX4);
    WPtrs ws; ws.w[0] = Wq; ws.w[1] = Wk; ws.w[2] = Wv; ws.w[3] = Wo;
    round_w4_kernel<<<(4*NW4)/256, 256>>>(ws, wr, NW4);

    cudaFuncSetAttribute(tf32_gemm<true>,  cudaFuncAttributeMaxDynamicSharedMemorySize, GEMM_SMEM);
    cudaFuncSetAttribute(tf32_gemm<false>, cudaFuncAttributeMaxDynamicSharedMemorySize, GEMM_SMEM);

    // Fused QKV GEMM: W rows 0..6143 of g_Wr (Wq,Wk,Wv stacked)
    GemmOuts qkv;
    qkv.out[0] = qp;  qkv.out[1] = kp;  qkv.out[2] = vp;
    qkv.bias[0] = bq; qkv.bias[1] = bk; qkv.bias[2] = bv;
    dim3 qkvgrid(3*HIDDEN/GBN, ROWS/GBM);   // (48, 32) = 1536 CTAs
    tf32_gemm<true><<<qkvgrid, 128, GEMM_SMEM>>>(xr, wr, qkv);

    cudaFuncSetAttribute(attn_tf32, cudaFuncAttributeMaxDynamicSharedMemorySize, (int)ATT_SMEM);
    dim3 agrid(SEQ/AQ, NHEADS, BATCH);  // (16, 16, 2)
    attn_tf32<<<agrid, 512, ATT_SMEM>>>(qp, kp, vp, mask, cp);

    // Output GEMM: Wo at rows 3*2048.. of g_Wr
    GemmOuts og;
    og.out[0] = out; og.out[1] = out; og.out[2] = out;
    og.bias[0] = bo; og.bias[1] = bo; og.bias[2] = bo;
    dim3 ogrid(HIDDEN/GBN, ROWS/GBM);   // (16, 32) = 512 CTAs
    tf32_gemm<false><<<ogrid, 128, GEMM_SMEM>>>(cp, wr + 3*HIDDEN*HIDDEN, og);
}

// round 10
// speedup vs baseline: 1.1405x; 1.0484x over previous
#include <cuda_runtime.h>
#include <math.h>
#include <cstdint>

#define HIDDEN 2048
#define NHEADS 16
#define HDIM   128
#define BATCH  2
#define SEQ    2048
#define ROWS   (BATCH*SEQ)             // 4096
#define SCALE  0.08838834764831845f    // 1/sqrt(128)
#define SCALE2 0.12752041986642899f    // SCALE * log2(e)
#define LOG2E  1.4426950408889634f

// Scratch (allocation-guard-safe)
__device__ float g_Q[ROWS*HIDDEN];
__device__ float g_K[ROWS*HIDDEN];
__device__ float g_V[ROWS*HIDDEN];
__device__ float g_C[ROWS*HIDDEN];
__device__ float g_Xr[ROWS*HIDDEN];          // tf32-rounded hidden_states
__device__ float g_Wr[4*HIDDEN*HIDDEN];      // tf32-rounded Wq,Wk,Wv,Wo

// ---------------------------------------------------------------------------
// Helpers
// ---------------------------------------------------------------------------
__device__ __forceinline__ unsigned f2tf(float f) {
    unsigned u; asm("cvt.rna.tf32.f32 %0, %1;" : "=r"(u) : "f"(f)); return u;
}
__device__ __forceinline__ float ex2(float x) {
    float r; asm("ex2.approx.f32 %0, %1;" : "=f"(r) : "f"(x)); return r;
}
__device__ __forceinline__ uint32_t smem_u32(const void* p) {
    uint32_t a; asm("{ .reg .u64 t; cvta.to.shared.u64 t, %1; cvt.u32.u64 %0, t; }"
                    : "=r"(a) : "l"(p));
    return a;
}
__device__ __forceinline__ void cpa16(uint32_t dst, const void* src) {
    asm volatile("cp.async.cg.shared.global [%0], [%1], 16;" :: "r"(dst), "l"(src));
}
#define CP_COMMIT()  asm volatile("cp.async.commit_group;" ::: "memory")
#define CP_WAIT(n)   asm volatile("cp.async.wait_group %0;" :: "n"(n) : "memory")

__device__ __forceinline__ void mma8(float* c, const unsigned* a, const unsigned* b) {
    asm volatile(
        "mma.sync.aligned.m16n8k8.row.col.f32.tf32.tf32.f32 "
        "{%0,%1,%2,%3}, {%4,%5,%6,%7}, {%8,%9}, {%0,%1,%2,%3};"
        : "+f"(c[0]), "+f"(c[1]), "+f"(c[2]), "+f"(c[3])
        : "r"(a[0]), "r"(a[1]), "r"(a[2]), "r"(a[3]), "r"(b[0]), "r"(b[1]));
}

// ---------------------------------------------------------------------------
// Elementwise tf32 pre-round
// ---------------------------------------------------------------------------
__global__ void round_tf32_kernel(const float* __restrict__ in, float* __restrict__ out, int n4) {
    int i = blockIdx.x * blockDim.x + threadIdx.x;
    if (i < n4) {
        float4 v = ((const float4*)in)[i];
        float4 o;
        o.x = __uint_as_float(f2tf(v.x));
        o.y = __uint_as_float(f2tf(v.y));
        o.z = __uint_as_float(f2tf(v.z));
        o.w = __uint_as_float(f2tf(v.w));
        ((float4*)out)[i] = o;
    }
}

struct WPtrs { const float* w[4]; };

__global__ void round_w4_kernel(WPtrs ws, float* __restrict__ out, int nw4) {
    int i = blockIdx.x * blockDim.x + threadIdx.x;   // over 4*nw4
    int which = i / nw4;
    int off   = i - which * nw4;
    float4 v = ((const float4*)ws.w[which])[off];
    float4 o;
    o.x = __uint_as_float(f2tf(v.x));
    o.y = __uint_as_float(f2tf(v.y));
    o.z = __uint_as_float(f2tf(v.z));
    o.w = __uint_as_float(f2tf(v.w));
    ((float4*)out)[i] = o;
}

// ---------------------------------------------------------------------------
// TF32 mma.sync GEMM (unchanged from R9 — proven):
// 128x128x32 CTA tile, 4 warps (64x64 warp tile, 1.0 LDS/MMA), 3-stage
// cp.async pipeline, 2 CTAs per SM. Fused-QKV via stacked-N output select.
// ---------------------------------------------------------------------------
#define GBM 128
#define GBN 128
#define GBK 32
#define AST 36
#define A_FLOATS (GBM*AST)                 // 4608
#define B_FLOATS (GBN*AST)                 // 4608
#define STG_FLOATS (A_FLOATS + B_FLOATS)   // 9216
#define NSTAGE 3
#define GEMM_SMEM (NSTAGE*STG_FLOATS*4)    // 110592 B
#define KCHUNKS (HIDDEN/GBK)               // 64

struct GemmOuts {
    float* out[3];
    const float* bias[3];
};

template<bool ROUND_OUT>
__global__ __launch_bounds__(128, 2) void tf32_gemm(
    const float* __restrict__ A, const float* __restrict__ W, GemmOuts go)
{
    extern __shared__ float sm[];
    const uint32_t sbase = smem_u32(sm);
    const int tid  = threadIdx.x;
    const int lane = tid & 31;
    const int warp = tid >> 5;          // 0..3
    const int g    = lane >> 2;
    const int l4   = lane & 3;
    const int mb   = (warp & 1) * 64;
    const int nb   = (warp >> 1) * 64;
    const int brow = blockIdx.y * GBM;
    const int bnT  = blockIdx.x * GBN;          // column in stacked-N space
    const int which = bnT >> 11;                // which weight matrix
    const int bn    = bnT & 2047;               // column within output
    float* C = go.out[which];
    const float* bias = go.bias[which];

    float acc[4][8][4];
    #pragma unroll
    for (int i = 0; i < 4; i++)
        #pragma unroll
        for (int j = 0; j < 8; j++)
            #pragma unroll
            for (int t = 0; t < 4; t++) acc[i][j][t] = 0.f;

    auto load_stage = [&](int c, int s) {
        const uint32_t dA = sbase + (uint32_t)s * (STG_FLOATS * 4);
        const uint32_t dB = dA + A_FLOATS * 4;
        const int k0 = c * GBK;
        #pragma unroll
        for (int i = 0; i < 8; i++) {
            int idx = tid + i * 128;
            int row = idx >> 3, kc = (idx & 7) * 4;
            cpa16(dA + row * (AST*4) + kc * 4,
                  &A[(size_t)(brow + row) * HIDDEN + k0 + kc]);
        }
        #pragma unroll
        for (int i = 0; i < 8; i++) {
            int idx = tid + i * 128;
            int row = idx >> 3, kc = (idx & 7) * 4;
            cpa16(dB + row * (AST*4) + kc * 4,
                  &W[(size_t)(bnT + row) * HIDDEN + k0 + kc]);
        }
        CP_COMMIT();
    };

    load_stage(0, 0);
    load_stage(1, 1);

    int s = 0;
    for (int c = 0; c < KCHUNKS; c++) {
        if (c == KCHUNKS - 1) { CP_WAIT(0); } else { CP_WAIT(1); }
        __syncthreads();
        if (c + 2 < KCHUNKS) load_stage(c + 2, (c + 2) % NSTAGE);

        const float* pA = sm + s * STG_FLOATS + mb * AST;
        const float* pB = sm + s * STG_FLOATS + A_FLOATS + nb * AST;

        #pragma unroll
        for (int ks = 0; ks < GBK; ks += 8) {
            unsigned af[4][4], bf[8][2];
            #pragma unroll
            for (int i = 0; i < 4; i++) {
                const float* p0 = pA + (i*16 + g) * AST + ks + l4;
                af[i][0] = __float_as_uint(p0[0]);
                af[i][1] = __float_as_uint(p0[8*AST]);
                af[i][2] = __float_as_uint(p0[4]);
                af[i][3] = __float_as_uint(p0[8*AST + 4]);
            }
            #pragma unroll
            for (int j = 0; j < 8; j++) {
                const float* p0 = pB + (j*8 + g) * AST + ks + l4;
                bf[j][0] = __float_as_uint(p0[0]);
                bf[j][1] = __float_as_uint(p0[4]);
            }
            #pragma unroll
            for (int i = 0; i < 4; i++)
                #pragma unroll
                for (int j = 0; j < 8; j++)
                    mma8(acc[i][j], af[i], bf[j]);
        }
        s = (s == NSTAGE - 1) ? 0 : s + 1;
    }

    #pragma unroll
    for (int i = 0; i < 4; i++) {
        const int r0 = brow + mb + i*16 + g;
        #pragma unroll
        for (int j = 0; j < 8; j++) {
            const int col = bn + nb + j*8 + 2*l4;
            float b0 = bias[col], b1 = bias[col + 1];
            float v0 = acc[i][j][0] + b0, v1 = acc[i][j][1] + b1;
            float v2 = acc[i][j][2] + b0, v3 = acc[i][j][3] + b1;
            if (ROUND_OUT) {
                v0 = __uint_as_float(f2tf(v0)); v1 = __uint_as_float(f2tf(v1));
                v2 = __uint_as_float(f2tf(v2)); v3 = __uint_as_float(f2tf(v3));
            }
            float2 w0 = {v0, v1}, w1 = {v2, v3};
            *(float2*)&C[(size_t)r0 * HIDDEN + col]       = w0;
            *(float2*)&C[(size_t)(r0 + 8) * HIDDEN + col] = w1;
        }
    }
}

// ---------------------------------------------------------------------------
// Flash attention, tf32 mma.sync, register-resident log2-domain softmax.
// 128 q-rows per block, 256 threads / 8 warps, 128 keys per iter.
// Warp tile 64x32 for BOTH QK^T and PV -> 1.5 LDS/HMMA (was 2.0).
//   mb=(warp&1)*64 picks q half; wc=warp>>1 picks 32-wide key block (QK)
//   or 32-wide headdim block (PV).
// V has its own smem stride VW=136 (bank 8*l4+g: conflict-free for the
// l4-row read pattern); Q/K/S keep 132 (bank 4*g+l4: conflict-free for
// the g-row pattern). S aliases K (dead after QK^T).
// ---------------------------------------------------------------------------
#define AQ  128
#define AKK 128
#define QW  132    // Q/K/S row stride
#define VW  136    // V row stride (conflict-free for PV B-operand reads)
#define OQ  0
#define OK  (AQ*QW)                 // 16896   (K tile; S aliases this)
#define OV  (OK + AKK*QW)           // 33792   (V tile, stride VW)
#define OMX (OV + AKK*VW)           // 51200
#define OL  (OMX + AQ)              // 51328
#define OPM (OL + AQ)               // 51456   pmax[4][128]
#define OPS (OPM + 512)             // 51968   psum[4][128]
#define ATT_FLOATS (OPS + 512)      // 52480
#define ATT_SMEM (ATT_FLOATS * 4)   // 209920 bytes

__global__ __launch_bounds__(256, 1) void attn_tf32(
    const float* __restrict__ Q, const float* __restrict__ K,
    const float* __restrict__ V, const float* __restrict__ mask,
    float* __restrict__ O)
{
    extern __shared__ float sm[];
    const uint32_t sbase = smem_u32(sm);
    float* sQ  = sm + OQ;
    float* sK  = sm + OK;
    float* sV  = sm + OV;
    float* sS  = sm + OK;      // alias: S overwrites K after QK^T
    float* sMx = sm + OMX;
    float* sL  = sm + OL;
    float* pmax = sm + OPM;
    float* psum = sm + OPS;

    const int tid  = threadIdx.x;
    const int lane = tid & 31;
    const int warp = tid >> 5;          // 0..7
    const int g    = lane >> 2;
    const int l4   = lane & 3;
    const int mb   = (warp & 1) * 64;   // q block (64 rows)
    const int wc   = warp >> 1;         // 0..3
    const int cb   = wc * 32;           // key block (QK) / headdim block (PV)
    const int qt = blockIdx.x, h = blockIdx.y, b = blockIdx.z;
    const size_t base = (size_t)b * SEQ * HIDDEN + (size_t)h * HDIM;

    // resident Q tile (already tf32-rounded bits)
    for (int it = tid; it < AQ*HDIM/4; it += 256) {
        int r = it >> 5, c = (it & 31) * 4;
        *(float4*)&sQ[r*QW + c] =
            *(const float4*)&Q[base + (size_t)(qt*AQ + r)*HIDDEN + c];
    }
    if (tid < AQ) { sMx[tid] = -1e30f; sL[tid] = 0.f; }

    float oacc[4][4][4];
    #pragma unroll
    for (int i = 0; i < 4; i++)
        #pragma unroll
        for (int j = 0; j < 4; j++)
            #pragma unroll
            for (int t = 0; t < 4; t++) oacc[i][j][t] = 0.f;

    for (int kt = 0; kt < SEQ/AKK; kt++) {      // 16 iterations
        __syncthreads();   // (1) prior PV done: K/S, V buffers + partials free

        // issue K loads (group 1), then V loads (group 2)
        {
            const uint32_t kdst = sbase + OK*4;
            const uint32_t vdst = sbase + OV*4;
            #pragma unroll
            for (int i = 0; i < 16; i++) {
                int it = tid + i*256;
                int r = it >> 5, c = (it & 31) * 4;
                cpa16(kdst + (r*QW + c)*4,
                      &K[base + (size_t)(kt*AKK + r)*HIDDEN + c]);
            }
            CP_COMMIT();
            #pragma unroll
            for (int i = 0; i < 16; i++) {
                int it = tid + i*256;
                int r = it >> 5, c = (it & 31) * 4;
                cpa16(vdst + (r*VW + c)*4,
                      &V[base + (size_t)(kt*AKK + r)*HIDDEN + c]);
            }
            CP_COMMIT();
        }

        // mask values for this tile (log2 domain), overlap with K load
        float ml[4][2];
        {
            const float* mrow = &mask[(size_t)b*SEQ + kt*AKK];
            #pragma unroll
            for (int j = 0; j < 4; j++) {
                float2 mv = *(const float2*)&mrow[cb + j*8 + 2*l4];
                ml[j][0] = mv.x * LOG2E;
                ml[j][1] = mv.y * LOG2E;
            }
        }

        CP_WAIT(1);        // K arrived (V may still be in flight)
        __syncthreads();   // (2) K visible to all warps

        // ---- S = Q K^T on warp tile [mb:mb+64] x [cb:cb+32]
        float sacc[4][4][4];
        #pragma unroll
        for (int i = 0; i < 4; i++)
            #pragma unroll
            for (int j = 0; j < 4; j++)
                #pragma unroll
                for (int t = 0; t < 4; t++) sacc[i][j][t] = 0.f;

        #pragma unroll
        for (int ks = 0; ks < HDIM; ks += 8) {
            unsigned af[4][4], bf[4][2];
            #pragma unroll
            for (int i = 0; i < 4; i++) {
                const float* p0 = &sQ[(mb + i*16 + g)*QW + ks + l4];
                af[i][0] = __float_as_uint(p0[0]);
                af[i][1] = __float_as_uint(p0[8*QW]);
                af[i][2] = __float_as_uint(p0[4]);
                af[i][3] = __float_as_uint(p0[8*QW + 4]);
            }
            #pragma unroll
            for (int j = 0; j < 4; j++) {
                const float* p0 = &sK[(cb + j*8 + g)*QW + ks + l4];
                bf[j][0] = __float_as_uint(p0[0]);
                bf[j][1] = __float_as_uint(p0[4]);
            }
            #pragma unroll
            for (int i = 0; i < 4; i++)
                #pragma unroll
                for (int j = 0; j < 4; j++)
                    mma8(sacc[i][j], af[i], bf[j]);
        }

        // scale + mask in log2 domain (registers)
        #pragma unroll
        for (int i = 0; i < 4; i++)
            #pragma unroll
            for (int j = 0; j < 4; j++) {
                sacc[i][j][0] = sacc[i][j][0]*SCALE2 + ml[j][0];
                sacc[i][j][1] = sacc[i][j][1]*SCALE2 + ml[j][1];
                sacc[i][j][2] = sacc[i][j][2]*SCALE2 + ml[j][0];
                sacc[i][j][3] = sacc[i][j][3]*SCALE2 + ml[j][1];
            }

        // ---- per-row max partials (registers + quad shuffles)
        float mloc[4][2];
        #pragma unroll
        for (int i = 0; i < 4; i++)
            #pragma unroll
            for (int p = 0; p < 2; p++) {
                float m = -1e30f;
                #pragma unroll
                for (int j = 0; j < 4; j++)
                    m = fmaxf(m, fmaxf(sacc[i][j][2*p], sacc[i][j][2*p+1]));
                m = fmaxf(m, __shfl_xor_sync(0xffffffffu, m, 1));
                m = fmaxf(m, __shfl_xor_sync(0xffffffffu, m, 2));
                mloc[i][p] = m;
            }
        if (l4 == 0) {
            #pragma unroll
            for (int i = 0; i < 4; i++)
                #pragma unroll
                for (int p = 0; p < 2; p++)
                    pmax[wc*AQ + mb + i*16 + p*8 + g] = mloc[i][p];
        }
        __syncthreads();   // (3) pmax visible; ALL K reads complete

        // ---- combine maxes, exponentiate in registers, store P, sum
        float mtv[4][2], fv[4][2], lsum[4][2];
        #pragma unroll
        for (int i = 0; i < 4; i++)
            #pragma unroll
            for (int p = 0; p < 2; p++) {
                int r = mb + i*16 + p*8 + g;
                float mo = sMx[r];
                float mt = fmaxf(fmaxf(pmax[r], pmax[AQ+r]),
                                 fmaxf(pmax[2*AQ+r], pmax[3*AQ+r]));
                mt = fmaxf(mo, mt);
                mtv[i][p] = mt;
                fv[i][p]  = ex2(mo - mt);
                lsum[i][p] = 0.f;
            }
        #pragma unroll
        for (int i = 0; i < 4; i++)
            #pragma unroll
            for (int j = 0; j < 4; j++)
                #pragma unroll
                for (int p = 0; p < 2; p++) {
                    float p0 = __uint_as_float(f2tf(ex2(sacc[i][j][2*p]   - mtv[i][p])));
                    float p1 = __uint_as_float(f2tf(ex2(sacc[i][j][2*p+1] - mtv[i][p])));
                    lsum[i][p] += p0 + p1;
                    float2 pv = {p0, p1};
                    *(float2*)&sS[(mb + i*16 + p*8 + g)*QW + cb + j*8 + 2*l4] = pv;
                }
        #pragma unroll
        for (int i = 0; i < 4; i++)
            #pragma unroll
            for (int p = 0; p < 2; p++) {
                float l = lsum[i][p];
                l += __shfl_xor_sync(0xffffffffu, l, 1);
                l += __shfl_xor_sync(0xffffffffu, l, 2);
                lsum[i][p] = l;
            }
        if (l4 == 0) {
            #pragma unroll
            for (int i = 0; i < 4; i++)
                #pragma unroll
                for (int p = 0; p < 2; p++)
                    psum[wc*AQ + mb + i*16 + p*8 + g] = lsum[i][p];
        }

        CP_WAIT(0);        // V arrived
        __syncthreads();   // (4) psum + P + V visible

        // owner updates running stats (warps with wc==0 cover all 128 rows)
        if (wc == 0 && l4 == 0) {
            #pragma unroll
            for (int i = 0; i < 4; i++)
                #pragma unroll
                for (int p = 0; p < 2; p++) {
                    int r = mb + i*16 + p*8 + g;
                    float ls = psum[r] + psum[AQ+r] + psum[2*AQ+r] + psum[3*AQ+r];
                    sL[r]  = sL[r]*fv[i][p] + ls;
                    sMx[r] = mtv[i][p];
                }
        }

        // rescale O and accumulate P V on warp tile [mb:mb+64] x d[cb:cb+32]
        #pragma unroll
        for (int i = 0; i < 4; i++)
            #pragma unroll
            for (int j = 0; j < 4; j++) {
                oacc[i][j][0] *= fv[i][0]; oacc[i][j][1] *= fv[i][0];
                oacc[i][j][2] *= fv[i][1]; oacc[i][j][3] *= fv[i][1];
            }
        #pragma unroll
        for (int ks = 0; ks < AKK; ks += 8) {
            unsigned af[4][4], bf[4][2];
            #pragma unroll
            for (int i = 0; i < 4; i++) {
                const float* p0 = &sS[(mb + i*16 + g)*QW + ks + l4];
                af[i][0] = __float_as_uint(p0[0]);
                af[i][1] = __float_as_uint(p0[8*QW]);
                af[i][2] = __float_as_uint(p0[4]);
                af[i][3] = __float_as_uint(p0[8*QW + 4]);
            }
            #pragma unroll
            for (int j = 0; j < 4; j++) {
                const float* p0 = &sV[(ks + l4)*VW + cb + j*8 + g];
                bf[j][0] = __float_as_uint(p0[0]);
                bf[j][1] = __float_as_uint(p0[4*VW]);
            }
            #pragma unroll
            for (int i = 0; i < 4; i++)
                #pragma unroll
                for (int j = 0; j < 4; j++)
                    mma8(oacc[i][j], af[i], bf[j]);
        }
    }

    __syncthreads();       // final sL updates visible

    // normalize + write (tf32-rounded so Wo GEMM's A is pre-rounded)
    #pragma unroll
    for (int i = 0; i < 4; i++) {
        float i0 = 1.f / sL[mb + i*16 + g];
        float i1 = 1.f / sL[mb + i*16 + g + 8];
        #pragma unroll
        for (int j = 0; j < 4; j++) {
            int col = cb + j*8 + 2*l4;
            size_t r0 = base + (size_t)(qt*AQ + mb + i*16 + g    )*HIDDEN + col;
            size_t r1 = base + (size_t)(qt*AQ + mb + i*16 + g + 8)*HIDDEN + col;
            float2 v0 = { __uint_as_float(f2tf(oacc[i][j][0]*i0)),
                          __uint_as_float(f2tf(oacc[i][j][1]*i0)) };
            float2 v1 = { __uint_as_float(f2tf(oacc[i][j][2]*i1)),
                          __uint_as_float(f2tf(oacc[i][j][3]*i1)) };
            *(float2*)&O[r0] = v0;
            *(float2*)&O[r1] = v1;
        }
    }
}

// ---------------------------------------------------------------------------
extern "C" void kernel_launch(void* const* d_in, const int* in_sizes, int n_in,
                              void* d_out, int out_size) {
    const float* X    = (const float*)d_in[0];
    const float* mask = (const float*)d_in[1];
    const float* Wq   = (const float*)d_in[2];
    const float* bq   = (const float*)d_in[3];
    const float* Wk   = (const float*)d_in[4];
    const float* bk   = (const float*)d_in[5];
    const float* Wv   = (const float*)d_in[6];
    const float* bv   = (const float*)d_in[7];
    const float* Wo   = (const float*)d_in[8];
    const float* bo   = (const float*)d_in[9];
    float* out = (float*)d_out;

    float *qp, *kp, *vp, *cp, *xr, *wr;
    cudaGetSymbolAddress((void**)&qp, g_Q);
    cudaGetSymbolAddress((void**)&kp, g_K);
    cudaGetSymbolAddress((void**)&vp, g_V);
    cudaGetSymbolAddress((void**)&cp, g_C);
    cudaGetSymbolAddress((void**)&xr, g_Xr);
    cudaGetSymbolAddress((void**)&wr, g_Wr);

    const int NX4 = ROWS*HIDDEN/4, NW4 = HIDDEN*HIDDEN/4;
    round_tf32_kernel<<<(NX4+255)/256, 256>>>(X, xr, NX4);
    WPtrs ws; ws.w[0] = Wq; ws.w[1] = Wk; ws.w[2] = Wv; ws.w[3] = Wo;
    round_w4_kernel<<<(4*NW4)/256, 256>>>(ws, wr, NW4);

    cudaFuncSetAttribute(tf32_gemm<true>,  cudaFuncAttributeMaxDynamicSharedMemorySize, GEMM_SMEM);
    cudaFuncSetAttribute(tf32_gemm<false>, cudaFuncAttributeMaxDynamicSharedMemorySize, GEMM_SMEM);

    // Fused QKV GEMM: W rows 0..6143 of g_Wr (Wq,Wk,Wv stacked)
    GemmOuts qkv;
    qkv.out[0] = qp;  qkv.out[1] = kp;  qkv.out[2] = vp;
    qkv.bias[0] = bq; qkv.bias[1] = bk; qkv.bias[2] = bv;
    dim3 qkvgrid(3*HIDDEN/GBN, ROWS/GBM);   // (48, 32) = 1536 CTAs
    tf32_gemm<true><<<qkvgrid, 128, GEMM_SMEM>>>(xr, wr, qkv);

    cudaFuncSetAttribute(attn_tf32, cudaFuncAttributeMaxDynamicSharedMemorySize, (int)ATT_SMEM);
    dim3 agrid(SEQ/AQ, NHEADS, BATCH);  // (16, 16, 2)
    attn_tf32<<<agrid, 256, ATT_SMEM>>>(qp, kp, vp, mask, cp);

    // Output GEMM: Wo at rows 3*2048.. of g_Wr
    GemmOuts og;
    og.out[0] = out; og.out[1] = out; og.out[2] = out;
    og.bias[0] = bo; og.bias[1] = bo; og.bias[2] = bo;
    dim3 ogrid(HIDDEN/GBN, ROWS/GBM);   // (16, 32) = 512 CTAs
    tf32_gemm<false><<<ogrid, 128, GEMM_SMEM>>>(cp, wr + 3*HIDDEN*HIDDEN, og);
}

// round 11
// speedup vs baseline: 2.0528x; 1.7999x over previous
#include <cuda_runtime.h>
#include <cuda_fp16.h>
#include <math.h>
#include <cstdint>

#define HIDDEN 2048
#define NHEADS 16
#define HDIM   128
#define BATCH  2
#define SEQ    2048
#define ROWS   (BATCH*SEQ)             // 4096
#define SCALE2 0.12752041986642899f    // (1/sqrt(128)) * log2(e)
#define LOG2E  1.4426950408889634f

// Scratch (allocation-guard-safe), fp16
__device__ __half g_Qh[ROWS*HIDDEN];
__device__ __half g_Kh[ROWS*HIDDEN];
__device__ __half g_Vt[ROWS*HIDDEN];     // transposed: [b][h][d][seq]
__device__ __half g_Ch[ROWS*HIDDEN];     // ctx (attention output)
__device__ __half g_Xh[ROWS*HIDDEN];     // f16 hidden_states
__device__ __half g_Wh[4*HIDDEN*HIDDEN]; // f16 Wq,Wk,Wv,Wo stacked

// ---------------------------------------------------------------------------
// Helpers
// ---------------------------------------------------------------------------
__device__ __forceinline__ float ex2(float x) {
    float r; asm("ex2.approx.f32 %0, %1;" : "=f"(r) : "f"(x)); return r;
}
__device__ __forceinline__ uint32_t smem_u32(const void* p) {
    uint32_t a; asm("{ .reg .u64 t; cvta.to.shared.u64 t, %1; cvt.u32.u64 %0, t; }"
                    : "=r"(a) : "l"(p));
    return a;
}
__device__ __forceinline__ void cpa16(uint32_t dst, const void* src) {
    asm volatile("cp.async.cg.shared.global [%0], [%1], 16;" :: "r"(dst), "l"(src));
}
#define CP_COMMIT()  asm volatile("cp.async.commit_group;" ::: "memory")
#define CP_WAIT(n)   asm volatile("cp.async.wait_group %0;" :: "n"(n) : "memory")

// fp16 MMA, fp32 accumulate: D(16x8) += A(16x16) B(16x8)
__device__ __forceinline__ void mma16(float* c, const unsigned* a, const unsigned* b) {
    asm volatile(
        "mma.sync.aligned.m16n8k16.row.col.f32.f16.f16.f32 "
        "{%0,%1,%2,%3}, {%4,%5,%6,%7}, {%8,%9}, {%0,%1,%2,%3};"
        : "+f"(c[0]), "+f"(c[1]), "+f"(c[2]), "+f"(c[3])
        : "r"(a[0]), "r"(a[1]), "r"(a[2]), "r"(a[3]), "r"(b[0]), "r"(b[1]));
}

// ---------------------------------------------------------------------------
// f32 -> f16 pre-convert
// ---------------------------------------------------------------------------
__global__ void conv_half_kernel(const float* __restrict__ in, __half* __restrict__ out, int n4) {
    int i = blockIdx.x * blockDim.x + threadIdx.x;
    if (i < n4) {
        float4 v = ((const float4*)in)[i];
        __half2 h0 = __floats2half2_rn(v.x, v.y);
        __half2 h1 = __floats2half2_rn(v.z, v.w);
        uint2 o = { *(uint32_t*)&h0, *(uint32_t*)&h1 };
        ((uint2*)out)[i] = o;
    }
}

struct WPtrs { const float* w[4]; };

__global__ void conv_w4_kernel(WPtrs ws, __half* __restrict__ out, int nw4) {
    int i = blockIdx.x * blockDim.x + threadIdx.x;   // over 4*nw4
    int which = i / nw4;
    int off   = i - which * nw4;
    float4 v = ((const float4*)ws.w[which])[off];
    __half2 h0 = __floats2half2_rn(v.x, v.y);
    __half2 h1 = __floats2half2_rn(v.z, v.w);
    uint2 o = { *(uint32_t*)&h0, *(uint32_t*)&h1 };
    ((uint2*)out)[i] = o;
}

// ---------------------------------------------------------------------------
// FP16 mma.sync GEMM: out = A(half)[M,K] @ W(half)[N,K]^T + bias, f32 acc
// 128x128x64 CTA tile, 4 warps (64x64 warp tile), 3-stage cp.async,
// 2 CTAs/SM. Stacked-N fused QKV; V (which==2) stored TRANSPOSED
// [b][h][d][seq] for attention's key-major PV operand.
// OUTMODE: 0 = half out (QKV), 1 = float out (final).
// ---------------------------------------------------------------------------
#define GBM 128
#define GBN 128
#define GBK 64                              // k per chunk (halves)
#define ASTH 72                             // smem row stride in halves (144B)
#define STG_BYTES (2*GBM*ASTH*2)            // A + B per stage = 36864 B
#define NSTAGE 3
#define GEMM_SMEM (NSTAGE*STG_BYTES)        // 110592 B
#define KCHUNKS (HIDDEN/GBK)                // 32

struct GemmOuts {
    void* out[3];
    const float* bias[3];
};

template<int OUTMODE>
__global__ __launch_bounds__(128, 2) void h16_gemm(
    const __half* __restrict__ A, const __half* __restrict__ W, GemmOuts go)
{
    extern __shared__ char smemc[];
    __half* sm = (__half*)smemc;
    const uint32_t sbase = smem_u32(sm);
    const int tid  = threadIdx.x;
    const int lane = tid & 31;
    const int warp = tid >> 5;          // 0..3
    const int g    = lane >> 2;
    const int l4   = lane & 3;
    const int mb   = (warp & 1) * 64;
    const int nb   = (warp >> 1) * 64;
    const int brow = blockIdx.y * GBM;
    const int bnT  = blockIdx.x * GBN;          // column in stacked-N space
    const int which = bnT >> 11;
    const int bn    = bnT & 2047;
    const float* bias = go.bias[which];

    float acc[4][8][4];
    #pragma unroll
    for (int i = 0; i < 4; i++)
        #pragma unroll
        for (int j = 0; j < 8; j++)
            #pragma unroll
            for (int t = 0; t < 4; t++) acc[i][j][t] = 0.f;

    auto load_stage = [&](int c, int s) {
        const uint32_t dA = sbase + (uint32_t)s * STG_BYTES;
        const uint32_t dB = dA + GBM*ASTH*2;
        const int k0 = c * GBK;
        #pragma unroll
        for (int i = 0; i < 8; i++) {            // A: 128 rows x 64 halves
            int idx = tid + i * 128;
            int row = idx >> 3, kc = (idx & 7) * 8;   // halves
            cpa16(dA + (row * ASTH + kc) * 2,
                  &A[(size_t)(brow + row) * HIDDEN + k0 + kc]);
        }
        #pragma unroll
        for (int i = 0; i < 8; i++) {            // B: 128 rows x 64 halves
            int idx = tid + i * 128;
            int row = idx >> 3, kc = (idx & 7) * 8;
            cpa16(dB + (row * ASTH + kc) * 2,
                  &W[(size_t)(bnT + row) * HIDDEN + k0 + kc]);
        }
        CP_COMMIT();
    };

    load_stage(0, 0);
    load_stage(1, 1);

    int s = 0;
    for (int c = 0; c < KCHUNKS; c++) {
        if (c == KCHUNKS - 1) { CP_WAIT(0); } else { CP_WAIT(1); }
        __syncthreads();
        if (c + 2 < KCHUNKS) load_stage(c + 2, (c + 2) % NSTAGE);

        const __half* pA = sm + (size_t)s * (STG_BYTES/2) + mb * ASTH;
        const __half* pB = sm + (size_t)s * (STG_BYTES/2) + GBM*ASTH + nb * ASTH;

        #pragma unroll
        for (int ks = 0; ks < GBK; ks += 16) {
            unsigned af[4][4], bf[8][2];
            #pragma unroll
            for (int i = 0; i < 4; i++) {
                const __half* p0 = pA + (i*16 + g) * ASTH + ks + 2*l4;
                af[i][0] = *(const unsigned*)(p0);
                af[i][1] = *(const unsigned*)(p0 + 8*ASTH);
                af[i][2] = *(const unsigned*)(p0 + 8);
                af[i][3] = *(const unsigned*)(p0 + 8*ASTH + 8);
            }
            #pragma unroll
            for (int j = 0; j < 8; j++) {
                const __half* p0 = pB + (j*8 + g) * ASTH + ks + 2*l4;
                bf[j][0] = *(const unsigned*)(p0);
                bf[j][1] = *(const unsigned*)(p0 + 8);
            }
            #pragma unroll
            for (int i = 0; i < 4; i++)
                #pragma unroll
                for (int j = 0; j < 8; j++)
                    mma16(acc[i][j], af[i], bf[j]);
        }
        s = (s == NSTAGE - 1) ? 0 : s + 1;
    }

    // epilogue
    if (OUTMODE == 1) {
        float* C = (float*)go.out[which];
        #pragma unroll
        for (int i = 0; i < 4; i++) {
            const int r0 = brow + mb + i*16 + g;
            #pragma unroll
            for (int j = 0; j < 8; j++) {
                const int col = bn + nb + j*8 + 2*l4;
                float b0 = bias[col], b1 = bias[col + 1];
                float2 w0 = { acc[i][j][0] + b0, acc[i][j][1] + b1 };
                float2 w1 = { acc[i][j][2] + b0, acc[i][j][3] + b1 };
                *(float2*)&C[(size_t)r0 * HIDDEN + col]       = w0;
                *(float2*)&C[(size_t)(r0 + 8) * HIDDEN + col] = w1;
            }
        }
    } else if (which != 2) {
        __half* C = (__half*)go.out[which];
        #pragma unroll
        for (int i = 0; i < 4; i++) {
            const int r0 = brow + mb + i*16 + g;
            #pragma unroll
            for (int j = 0; j < 8; j++) {
                const int col = bn + nb + j*8 + 2*l4;
                float b0 = bias[col], b1 = bias[col + 1];
                __half2 h0 = __floats2half2_rn(acc[i][j][0] + b0, acc[i][j][1] + b1);
                __half2 h1 = __floats2half2_rn(acc[i][j][2] + b0, acc[i][j][3] + b1);
                *(__half2*)&C[(size_t)r0 * HIDDEN + col]       = h0;
                *(__half2*)&C[(size_t)(r0 + 8) * HIDDEN + col] = h1;
            }
        }
    } else {
        // V: store transposed [b][h][d][seq]
        __half* Vt = (__half*)go.out[2];
        #pragma unroll
        for (int i = 0; i < 4; i++) {
            const int r0 = brow + mb + i*16 + g;      // token
            const int b  = r0 >> 11;
            const int s0 = r0 & 2047;
            #pragma unroll
            for (int j = 0; j < 8; j++) {
                const int col = bn + nb + j*8 + 2*l4; // h*128 + d
                const int hh = col >> 7, d = col & 127;
                float b0 = bias[col], b1 = bias[col + 1];
                size_t base0 = ((size_t)(b*NHEADS + hh)*HDIM + d) * SEQ;
                Vt[base0 + s0]            = __float2half_rn(acc[i][j][0] + b0);
                Vt[base0 + SEQ + s0]      = __float2half_rn(acc[i][j][1] + b1);
                Vt[base0 + s0 + 8]        = __float2half_rn(acc[i][j][2] + b0);
                Vt[base0 + SEQ + s0 + 8]  = __float2half_rn(acc[i][j][3] + b1);
            }
        }
    }
}

// ---------------------------------------------------------------------------
// FP16 flash attention, f32 softmax (log2 domain, register-resident).
// 128 q-rows per block, 256 threads / 8 warps, 128 keys per iter.
// Warp tile 64x32 for QK^T and PV. S (f16 P) aliases K. V is pre-transposed
// global [b][h][d][seq] so PV's B-fragment (key pairs) is contiguous.
// ---------------------------------------------------------------------------
#define AQ  128
#define AKK 128
#define QWH 136                        // row stride in halves (272 B)
#define OQ_B  0
#define OK_B  (AQ*QWH*2)               // 34816  (K tile; S aliases)
#define OV_B  (OK_B + AKK*QWH*2)       // 69632  (Vt tile: 128 d-rows)
#define OST_B (OV_B + AKK*QWH*2)       // 104448 (f32 stats)
#define OMX_F 0
#define OL_F  128
#define OPM_F 256                      // pmax[4][128]
#define OPS_F 768                      // psum[4][128]
#define ATT_SMEM (OST_B + 1280*4)      // 109568 B

__global__ __launch_bounds__(256, 1) void attn_h16(
    const __half* __restrict__ Q, const __half* __restrict__ K,
    const __half* __restrict__ Vt, const float* __restrict__ mask,
    __half* __restrict__ O)
{
    extern __shared__ char smemc[];
    const uint32_t sbase = smem_u32(smemc);
    __half* sQh = (__half*)(smemc + OQ_B);
    __half* sKh = (__half*)(smemc + OK_B);
    __half* sVh = (__half*)(smemc + OV_B);
    __half* sSh = (__half*)(smemc + OK_B);   // alias
    float* stats = (float*)(smemc + OST_B);
    float* sMx  = stats + OMX_F;
    float* sL   = stats + OL_F;
    float* pmax = stats + OPM_F;
    float* psum = stats + OPS_F;

    const int tid  = threadIdx.x;
    const int lane = tid & 31;
    const int warp = tid >> 5;          // 0..7
    const int g    = lane >> 2;
    const int l4   = lane & 3;
    const int mb   = (warp & 1) * 64;   // q block
    const int wc   = warp >> 1;         // 0..3
    const int cb   = wc * 32;           // key cols (QK) / d cols (PV)
    const int qt = blockIdx.x, h = blockIdx.y, b = blockIdx.z;
    const size_t base  = (size_t)b * SEQ * HIDDEN + (size_t)h * HDIM;
    const size_t vbase = ((size_t)(b*NHEADS + h)) * HDIM * SEQ;

    // resident Q tile (16B vector copies)
    for (int it = tid; it < AQ*16; it += 256) {
        int r = it >> 4, c = (it & 15) * 8;
        *(uint4*)&sQh[r*QWH + c] =
            *(const uint4*)&Q[base + (size_t)(qt*AQ + r)*HIDDEN + c];
    }
    if (tid < AQ) { sMx[tid] = -1e30f; sL[tid] = 0.f; }

    float oacc[4][4][4];
    #pragma unroll
    for (int i = 0; i < 4; i++)
        #pragma unroll
        for (int j = 0; j < 4; j++)
            #pragma unroll
            for (int t = 0; t < 4; t++) oacc[i][j][t] = 0.f;

    for (int kt = 0; kt < SEQ/AKK; kt++) {      // 16 iterations
        __syncthreads();   // (1) prior PV done: K/S, V buffers + partials free

        // K (group 1), Vt (group 2)
        {
            const uint32_t kdst = sbase + OK_B;
            const uint32_t vdst = sbase + OV_B;
            #pragma unroll
            for (int i = 0; i < 8; i++) {
                int it = tid + i*256;
                int r = it >> 4, c = (it & 15) * 8;
                cpa16(kdst + (r*QWH + c)*2,
                      &K[base + (size_t)(kt*AKK + r)*HIDDEN + c]);
            }
            CP_COMMIT();
            #pragma unroll
            for (int i = 0; i < 8; i++) {
                int it = tid + i*256;
                int d = it >> 4, c = (it & 15) * 8;
                cpa16(vdst + (d*QWH + c)*2,
                      &Vt[vbase + (size_t)d*SEQ + kt*AKK + c]);
            }
            CP_COMMIT();
        }

        float ml[4][2];
        {
            const float* mrow = &mask[(size_t)b*SEQ + kt*AKK];
            #pragma unroll
            for (int j = 0; j < 4; j++) {
                float2 mv = *(const float2*)&mrow[cb + j*8 + 2*l4];
                ml[j][0] = mv.x * LOG2E;
                ml[j][1] = mv.y * LOG2E;
            }
        }

        CP_WAIT(1);        // K arrived
        __syncthreads();   // (2) K visible

        // ---- S = Q K^T on warp tile [mb:mb+64] x [cb:cb+32]
        float sacc[4][4][4];
        #pragma unroll
        for (int i = 0; i < 4; i++)
            #pragma unroll
            for (int j = 0; j < 4; j++)
                #pragma unroll
                for (int t = 0; t < 4; t++) sacc[i][j][t] = 0.f;

        #pragma unroll
        for (int ks = 0; ks < HDIM; ks += 16) {
            unsigned af[4][4], bf[4][2];
            #pragma unroll
            for (int i = 0; i < 4; i++) {
                const __half* p0 = &sQh[(mb + i*16 + g)*QWH + ks + 2*l4];
                af[i][0] = *(const unsigned*)(p0);
                af[i][1] = *(const unsigned*)(p0 + 8*QWH);
                af[i][2] = *(const unsigned*)(p0 + 8);
                af[i][3] = *(const unsigned*)(p0 + 8*QWH + 8);
            }
            #pragma unroll
            for (int j = 0; j < 4; j++) {
                const __half* p0 = &sKh[(cb + j*8 + g)*QWH + ks + 2*l4];
                bf[j][0] = *(const unsigned*)(p0);
                bf[j][1] = *(const unsigned*)(p0 + 8);
            }
            #pragma unroll
            for (int i = 0; i < 4; i++)
                #pragma unroll
                for (int j = 0; j < 4; j++)
                    mma16(sacc[i][j], af[i], bf[j]);
        }

        // scale + mask in log2 domain
        #pragma unroll
        for (int i = 0; i < 4; i++)
            #pragma unroll
            for (int j = 0; j < 4; j++) {
                sacc[i][j][0] = sacc[i][j][0]*SCALE2 + ml[j][0];
                sacc[i][j][1] = sacc[i][j][1]*SCALE2 + ml[j][1];
                sacc[i][j][2] = sacc[i][j][2]*SCALE2 + ml[j][0];
                sacc[i][j][3] = sacc[i][j][3]*SCALE2 + ml[j][1];
            }

        // per-row max partials
        float mloc[4][2];
        #pragma unroll
        for (int i = 0; i < 4; i++)
            #pragma unroll
            for (int p = 0; p < 2; p++) {
                float m = -1e30f;
                #pragma unroll
                for (int j = 0; j < 4; j++)
                    m = fmaxf(m, fmaxf(sacc[i][j][2*p], sacc[i][j][2*p+1]));
                m = fmaxf(m, __shfl_xor_sync(0xffffffffu, m, 1));
                m = fmaxf(m, __shfl_xor_sync(0xffffffffu, m, 2));
                mloc[i][p] = m;
            }
        if (l4 == 0) {
            #pragma unroll
            for (int i = 0; i < 4; i++)
                #pragma unroll
                for (int p = 0; p < 2; p++)
                    pmax[wc*AQ + mb + i*16 + p*8 + g] = mloc[i][p];
        }
        __syncthreads();   // (3) pmax visible; ALL K reads done (S may overwrite)

        // combine maxes, exponentiate, store f16 P, sum
        float mtv[4][2], fv[4][2], lsum[4][2];
        #pragma unroll
        for (int i = 0; i < 4; i++)
            #pragma unroll
            for (int p = 0; p < 2; p++) {
                int r = mb + i*16 + p*8 + g;
                float mo = sMx[r];
                float mt = fmaxf(fmaxf(pmax[r], pmax[AQ+r]),
                                 fmaxf(pmax[2*AQ+r], pmax[3*AQ+r]));
                mt = fmaxf(mo, mt);
                mtv[i][p] = mt;
                fv[i][p]  = ex2(mo - mt);
                lsum[i][p] = 0.f;
            }
        #pragma unroll
        for (int i = 0; i < 4; i++)
            #pragma unroll
            for (int j = 0; j < 4; j++)
                #pragma unroll
                for (int p = 0; p < 2; p++) {
                    float p0 = ex2(sacc[i][j][2*p]   - mtv[i][p]);
                    float p1 = ex2(sacc[i][j][2*p+1] - mtv[i][p]);
                    __half2 ph = __floats2half2_rn(p0, p1);
                    lsum[i][p] += __low2float(ph) + __high2float(ph);
                    *(__half2*)&sSh[(mb + i*16 + p*8 + g)*QWH + cb + j*8 + 2*l4] = ph;
                }
        #pragma unroll
        for (int i = 0; i < 4; i++)
            #pragma unroll
            for (int p = 0; p < 2; p++) {
                float l = lsum[i][p];
                l += __shfl_xor_sync(0xffffffffu, l, 1);
                l += __shfl_xor_sync(0xffffffffu, l, 2);
                lsum[i][p] = l;
            }
        if (l4 == 0) {
            #pragma unroll
            for (int i = 0; i < 4; i++)
                #pragma unroll
                for (int p = 0; p < 2; p++)
                    psum[wc*AQ + mb + i*16 + p*8 + g] = lsum[i][p];
        }

        CP_WAIT(0);        // Vt arrived
        __syncthreads();   // (4) psum + P + Vt visible

        if (wc == 0 && l4 == 0) {
            #pragma unroll
            for (int i = 0; i < 4; i++)
                #pragma unroll
                for (int p = 0; p < 2; p++) {
                    int r = mb + i*16 + p*8 + g;
                    float ls = psum[r] + psum[AQ+r] + psum[2*AQ+r] + psum[3*AQ+r];
                    sL[r]  = sL[r]*fv[i][p] + ls;
                    sMx[r] = mtv[i][p];
                }
        }

        // rescale O, accumulate P V on warp tile [mb:mb+64] x d[cb:cb+32]
        #pragma unroll
        for (int i = 0; i < 4; i++)
            #pragma unroll
            for (int j = 0; j < 4; j++) {
                oacc[i][j][0] *= fv[i][0]; oacc[i][j][1] *= fv[i][0];
                oacc[i][j][2] *= fv[i][1]; oacc[i][j][3] *= fv[i][1];
            }
        #pragma unroll
        for (int ks = 0; ks < AKK; ks += 16) {
            unsigned af[4][4], bf[4][2];
            #pragma unroll
            for (int i = 0; i < 4; i++) {
                const __half* p0 = &sSh[(mb + i*16 + g)*QWH + ks + 2*l4];
                af[i][0] = *(const unsigned*)(p0);
                af[i][1] = *(const unsigned*)(p0 + 8*QWH);
                af[i][2] = *(const unsigned*)(p0 + 8);
                af[i][3] = *(const unsigned*)(p0 + 8*QWH + 8);
            }
            #pragma unroll
            for (int j = 0; j < 4; j++) {
                const __half* p0 = &sVh[(cb + j*8 + g)*QWH + ks + 2*l4];
                bf[j][0] = *(const unsigned*)(p0);
                bf[j][1] = *(const unsigned*)(p0 + 8);
            }
            #pragma unroll
            for (int i = 0; i < 4; i++)
                #pragma unroll
                for (int j = 0; j < 4; j++)
                    mma16(oacc[i][j], af[i], bf[j]);
        }
    }

    __syncthreads();       // final sL updates visible

    // normalize + write ctx (f16, normal [token][hidden] layout)
    #pragma unroll
    for (int i = 0; i < 4; i++) {
        float i0 = 1.f / sL[mb + i*16 + g];
        float i1 = 1.f / sL[mb + i*16 + g + 8];
        #pragma unroll
        for (int j = 0; j < 4; j++) {
            int col = cb + j*8 + 2*l4;
            size_t r0 = base + (size_t)(qt*AQ + mb + i*16 + g    )*HIDDEN + col;
            size_t r1 = base + (size_t)(qt*AQ + mb + i*16 + g + 8)*HIDDEN + col;
            *(__half2*)&O[r0] = __floats2half2_rn(oacc[i][j][0]*i0, oacc[i][j][1]*i0);
            *(__half2*)&O[r1] = __floats2half2_rn(oacc[i][j][2]*i1, oacc[i][j][3]*i1);
        }
    }
}

// ---------------------------------------------------------------------------
extern "C" void kernel_launch(void* const* d_in, const int* in_sizes, int n_in,
                              void* d_out, int out_size) {
    const float* X    = (const float*)d_in[0];
    const float* mask = (const float*)d_in[1];
    const float* Wq   = (const float*)d_in[2];
    const float* bq   = (const float*)d_in[3];
    const float* Wk   = (const float*)d_in[4];
    const float* bk   = (const float*)d_in[5];
    const float* Wv   = (const float*)d_in[6];
    const float* bv   = (const float*)d_in[7];
    const float* Wo   = (const float*)d_in[8];
    const float* bo   = (const float*)d_in[9];
    float* out = (float*)d_out;

    __half *qp, *kp, *vtp, *cp, *xh, *wh;
    cudaGetSymbolAddress((void**)&qp,  g_Qh);
    cudaGetSymbolAddress((void**)&kp,  g_Kh);
    cudaGetSymbolAddress((void**)&vtp, g_Vt);
    cudaGetSymbolAddress((void**)&cp,  g_Ch);
    cudaGetSymbolAddress((void**)&xh,  g_Xh);
    cudaGetSymbolAddress((void**)&wh,  g_Wh);

    const int NX4 = ROWS*HIDDEN/4, NW4 = HIDDEN*HIDDEN/4;
    conv_half_kernel<<<(NX4+255)/256, 256>>>(X, xh, NX4);
    WPtrs ws; ws.w[0] = Wq; ws.w[1] = Wk; ws.w[2] = Wv; ws.w[3] = Wo;
    conv_w4_kernel<<<(4*NW4)/256, 256>>>(ws, wh, NW4);

    cudaFuncSetAttribute(h16_gemm<0>, cudaFuncAttributeMaxDynamicSharedMemorySize, GEMM_SMEM);
    cudaFuncSetAttribute(h16_gemm<1>, cudaFuncAttributeMaxDynamicSharedMemorySize, GEMM_SMEM);

    // Fused QKV GEMM (Wq,Wk,Wv stacked in g_Wh)
    GemmOuts qkv;
    qkv.out[0] = qp;  qkv.out[1] = kp;  qkv.out[2] = vtp;
    qkv.bias[0] = bq; qkv.bias[1] = bk; qkv.bias[2] = bv;
    dim3 qkvgrid(3*HIDDEN/GBN, ROWS/GBM);   // (48, 32)
    h16_gemm<0><<<qkvgrid, 128, GEMM_SMEM>>>(xh, wh, qkv);

    cudaFuncSetAttribute(attn_h16, cudaFuncAttributeMaxDynamicSharedMemorySize, (int)ATT_SMEM);
    dim3 agrid(SEQ/AQ, NHEADS, BATCH);  // (16, 16, 2)
    attn_h16<<<agrid, 256, ATT_SMEM>>>(qp, kp, vtp, mask, cp);

    // Output GEMM: Wo rows at offset 3*H*H, f32 out
    GemmOuts og;
    og.out[0] = out; og.out[1] = out; og.out[2] = out;
    og.bias[0] = bo; og.bias[1] = bo; og.bias[2] = bo;
    dim3 ogrid(HIDDEN/GBN, ROWS/GBM);   // (16, 32)
    h16_gemm<1><<<ogrid, 128, GEMM_SMEM>>>(cp, wh + 3*HIDDEN*HIDDEN, og);
}